// round 12
// baseline (speedup 1.0000x reference)
#include <cuda_runtime.h>
#include <cuda.h>
#include <cuda_fp16.h>
#include <cstdint>
#include <math.h>

#define NMAT 4096
#define INF  1024
#define OUTF 1024
#define NB   8
#define K1   9216
#define KTILE 64                   // fp16 per k-chunk = 128 bytes (SW128 atom)
#define KCH (K1 / KTILE)           // 144
#define SPLITK 8
#define KT_PER (KCH / SPLITK)      // 18
#define BM 128
#define BN 128
#define STAGES 3

#define TILE_BYTES (BM * 128)                  // 16384 per operand
#define STAGE_BYTES (2 * TILE_BYTES)           // 32768
#define SM_STAGE(s) (1024 + (s) * STAGE_BYTES)
#define SMEM_TOTAL (1024 + STAGES * STAGE_BYTES)   // 99328
#define NTILES 256

// ---------------- scratch (__device__ globals; no allocs allowed) ----------
__device__ __align__(128) __half g_A[(size_t)NMAT * K1];
__device__ __align__(128) __half g_W[(size_t)OUTF * K1];
__device__ unsigned g_cnt[NTILES];   // zero-init; self-resetting each run

// ---------------- PTX helpers (family-portable only: sm_90 class) ----------
__device__ __forceinline__ uint32_t smem_u32(const void* p) {
    uint32_t a;
    asm("{ .reg .u64 t; cvta.to.shared.u64 t, %1; cvt.u32.u64 %0, t; }" : "=r"(a) : "l"(p));
    return a;
}
#define MBAR_INIT(addr, cnt) \
    asm volatile("mbarrier.init.shared.b64 [%0], %1;" :: "r"(addr), "r"(cnt) : "memory")
#define MBAR_EXPECT_TX(addr, bytes) \
    asm volatile("mbarrier.arrive.expect_tx.shared.b64 _, [%0], %1;" :: "r"(addr), "r"(bytes) : "memory")
#define MBAR_WAIT(addr, ph) do {                                              \
    uint32_t _m = (addr); uint32_t _p = (ph); uint32_t _d;                    \
    asm volatile("{\n .reg .pred p;\n"                                        \
        " mbarrier.try_wait.parity.acquire.cta.shared::cta.b64 p, [%1], %2;\n"\
        " selp.b32 %0, 1, 0, p;\n}" : "=r"(_d) : "r"(_m), "r"(_p) : "memory");\
    if (!_d) {                                                                \
        asm volatile("{\n .reg .pred P1;\n"                                   \
            "W_%=:\n"                                                         \
            " mbarrier.try_wait.parity.acquire.cta.shared::cta.b64 P1, [%0], %1, 0x989680;\n" \
            " @P1 bra.uni D_%=;\n bra.uni W_%=;\nD_%=:\n}"                    \
            :: "r"(_m), "r"(_p) : "memory");                                  \
    }                                                                         \
} while (0)

__device__ __forceinline__ void tma_load_2d(uint32_t dst, const void* map,
                                            int cx, int cy, uint32_t mbar) {
    asm volatile(
        "cp.async.bulk.tensor.2d.shared::cta.global.tile.mbarrier::complete_tx::bytes "
        "[%0], [%1, {%2, %3}], [%4];"
        :: "r"(dst), "l"(map), "r"(cx), "r"(cy), "r"(mbar) : "memory");
}
__device__ __forceinline__ void ldsm_x4(uint32_t& r0, uint32_t& r1, uint32_t& r2,
                                        uint32_t& r3, uint32_t addr) {
    asm volatile("ldmatrix.sync.aligned.m8n8.x4.shared.b16 {%0,%1,%2,%3}, [%4];"
                 : "=r"(r0), "=r"(r1), "=r"(r2), "=r"(r3) : "r"(addr));
}
__device__ __forceinline__ void mma_f16(float& c0, float& c1, float& c2, float& c3,
                                        uint32_t a0, uint32_t a1, uint32_t a2, uint32_t a3,
                                        uint32_t b0, uint32_t b1) {
    asm volatile("mma.sync.aligned.m16n8k16.row.col.f32.f16.f16.f32 "
                 "{%0,%1,%2,%3}, {%4,%5,%6,%7}, {%8,%9}, {%0,%1,%2,%3};"
                 : "+f"(c0), "+f"(c1), "+f"(c2), "+f"(c3)
                 : "r"(a0), "r"(a1), "r"(a2), "r"(a3), "r"(b0), "r"(b1));
}

// ===========================================================================
// Stage 1: dense zero + 4-slot scatter (deterministic, single-thread writes)
// ===========================================================================
__global__ void build_A_kernel(const float* __restrict__ x) {
    int idx = blockIdx.x * blockDim.x + threadIdx.x;
    if (idx >= NMAT * INF) return;
    float v = x[idx];
    size_t rb = (size_t)(idx >> 10) * K1 + (idx & 1023);

    g_A[rb] = __float2half_rn(v / (1.0f + __expf(-v)));   // silu
    const __half hz = __float2half_rn(0.0f);
#pragma unroll
    for (int s = 1; s <= 8; s++) g_A[rb + s * 1024] = hz;

    float p = (v + 2.2f) * 2.5f;
    if (p >= 0.0f && p < 11.0f) {
        float pf = floorf(p);
        int iv = (int)pf;
        float u = p - pf;
        float u2 = u * u, u3 = u2 * u;
        const float i6 = 1.0f / 6.0f;
        float c0 = (-u3 + 3.0f * u2 - 3.0f * u + 1.0f) * i6;       // j = iv-3
        float c1 = (3.0f * u3 - 6.0f * u2 + 4.0f) * i6;            // j = iv-2
        float c2 = (-3.0f * u3 + 3.0f * u2 + 3.0f * u + 1.0f) * i6;// j = iv-1
        float c3 = u3 * i6;                                        // j = iv
        int j0 = iv - 3;
        if (j0 >= 0 && j0 < 8)         g_A[rb + (j0 + 1) * 1024] = __float2half_rn(c0);
        if (j0 + 1 >= 0 && j0 + 1 < 8) g_A[rb + (j0 + 2) * 1024] = __float2half_rn(c1);
        if (j0 + 2 >= 0 && j0 + 2 < 8) g_A[rb + (j0 + 3) * 1024] = __float2half_rn(c2);
        if (j0 + 3 >= 0 && j0 + 3 < 8) g_A[rb + (j0 + 4) * 1024] = __float2half_rn(c3);
    }
}

__global__ void pack_W_kernel(const float* __restrict__ bw,
                              const float* __restrict__ sw) {
    int idx = blockIdx.x * blockDim.x + threadIdx.x;
    if (idx >= OUTF * INF) return;
    size_t rb = (size_t)(idx >> 10) * K1 + (idx & 1023);
    g_W[rb] = __float2half_rn(bw[idx]);
    const float4* s4 = (const float4*)(sw + (size_t)idx * NB);
    float4 s0 = s4[0], s1 = s4[1];
    g_W[rb + 1 * 1024] = __float2half_rn(s0.x);
    g_W[rb + 2 * 1024] = __float2half_rn(s0.y);
    g_W[rb + 3 * 1024] = __float2half_rn(s0.z);
    g_W[rb + 4 * 1024] = __float2half_rn(s0.w);
    g_W[rb + 5 * 1024] = __float2half_rn(s1.x);
    g_W[rb + 6 * 1024] = __float2half_rn(s1.y);
    g_W[rb + 7 * 1024] = __float2half_rn(s1.z);
    g_W[rb + 8 * 1024] = __float2half_rn(s1.w);
}

// ===========================================================================
// GEMM: 128x128 tile, 8 warps (2x4, 64x32 warp tiles), TMA + mbarrier
// pipeline (3 stages, prefetch 2), serial split-K 8  [R10-proven structure]
// ===========================================================================
__global__ void __launch_bounds__(256, 2)
gemm_kernel(const __grid_constant__ CUtensorMap tma_a,
            const __grid_constant__ CUtensorMap tma_w,
            const float* __restrict__ bias, float* __restrict__ C) {
    extern __shared__ __align__(1024) char smem[];
    uint32_t sb = smem_u32(smem);

    const int tid = threadIdx.x;
    const int wid = tid >> 5;
    const int lane = tid & 31;
    const int warp_m = wid & 1;
    const int warp_n = wid >> 1;
    const int bm = blockIdx.y * BM;
    const int bn = blockIdx.x * BN;
    const int kz = blockIdx.z;
    const int kb0 = kz * KT_PER;
    const int tile = blockIdx.y * gridDim.x + blockIdx.x;

    if (tid == 0) {
#pragma unroll
        for (int s = 0; s < STAGES; s++) MBAR_INIT(sb + s * 8, 1);
    }
    __syncthreads();

    if (tid == 0) {
#pragma unroll
        for (int j = 0; j < 2; j++) {
            uint32_t st = sb + SM_STAGE(j);
            MBAR_EXPECT_TX(sb + j * 8, STAGE_BYTES);
            tma_load_2d(st,              &tma_a, (kb0 + j) * KTILE, bm, sb + j * 8);
            tma_load_2d(st + TILE_BYTES, &tma_w, (kb0 + j) * KTILE, bn, sb + j * 8);
        }
    }

    float acc[4][4][4];
#pragma unroll
    for (int i = 0; i < 4; i++)
#pragma unroll
        for (int j = 0; j < 4; j++)
#pragma unroll
            for (int q = 0; q < 4; q++) acc[i][j][q] = 0.0f;

    const int a_row = lane & 15;
    const int a_c16 = (lane >> 4) << 4;
    const int b_row = ((lane >> 4) << 3) + (lane & 7);
    const int b_c16 = ((lane >> 3) & 1) << 4;

    for (int j = 0; j < KT_PER; j++) {
        int s = j % STAGES;
        MBAR_WAIT(sb + s * 8, (j / STAGES) & 1);
        __syncthreads();   // all threads done reading stage (j+2)%3 before refill
        if (tid == 0 && j + 2 < KT_PER) {
            int jn = j + 2, sn = jn % STAGES;
            uint32_t st = sb + SM_STAGE(sn);
            MBAR_EXPECT_TX(sb + sn * 8, STAGE_BYTES);
            tma_load_2d(st,              &tma_a, (kb0 + jn) * KTILE, bm, sb + sn * 8);
            tma_load_2d(st + TILE_BYTES, &tma_w, (kb0 + jn) * KTILE, bn, sb + sn * 8);
        }

        uint32_t sA = sb + SM_STAGE(s);
        uint32_t sB = sA + TILE_BYTES;
#pragma unroll
        for (int kk = 0; kk < 4; kk++) {
            int k0b = kk * 32;
            uint32_t a[4][4];
#pragma unroll
            for (int mt = 0; mt < 4; mt++) {
                int row = warp_m * 64 + mt * 16 + a_row;
                uint32_t off = row * 128 + ((k0b + a_c16) ^ ((row & 7) << 4));
                ldsm_x4(a[mt][0], a[mt][1], a[mt][2], a[mt][3], sA + off);
            }
            uint32_t bf[4][2];
#pragma unroll
            for (int pq = 0; pq < 2; pq++) {
                int row = warp_n * 32 + pq * 16 + b_row;
                uint32_t off = row * 128 + ((k0b + b_c16) ^ ((row & 7) << 4));
                ldsm_x4(bf[2 * pq][0], bf[2 * pq][1], bf[2 * pq + 1][0], bf[2 * pq + 1][1],
                        sB + off);
            }
#pragma unroll
            for (int mt = 0; mt < 4; mt++)
#pragma unroll
                for (int nt = 0; nt < 4; nt++)
                    mma_f16(acc[mt][nt][0], acc[mt][nt][1], acc[mt][nt][2], acc[mt][nt][3],
                            a[mt][0], a[mt][1], a[mt][2], a[mt][3],
                            bf[nt][0], bf[nt][1]);
        }
    }

    // ---------------- serial split-K epilogue (self-resetting counters) ----
    if (kz == 0) {
#pragma unroll
        for (int mt = 0; mt < 4; mt++) {
            int row0 = bm + warp_m * 64 + mt * 16 + (lane >> 2);
#pragma unroll
            for (int nt = 0; nt < 4; nt++) {
                int col = bn + warp_n * 32 + nt * 8 + (lane & 3) * 2;
                float b0 = __ldg(bias + col);
                float b1 = __ldg(bias + col + 1);
                float2 v0 = make_float2(acc[mt][nt][0] + b0, acc[mt][nt][1] + b1);
                float2 v1 = make_float2(acc[mt][nt][2] + b0, acc[mt][nt][3] + b1);
                *(float2*)(C + (size_t)row0 * OUTF + col)       = v0;
                *(float2*)(C + (size_t)(row0 + 8) * OUTF + col) = v1;
            }
        }
        __threadfence();
        __syncthreads();
        if (tid == 0) atomicAdd(&g_cnt[tile], 1u);
    } else {
        if (tid == 0) {
            while (atomicAdd(&g_cnt[tile], 0u) < (unsigned)kz) __nanosleep(64);
        }
        __syncthreads();
        __threadfence();
#pragma unroll
        for (int mt = 0; mt < 4; mt++) {
            int row0 = bm + warp_m * 64 + mt * 16 + (lane >> 2);
#pragma unroll
            for (int nt = 0; nt < 4; nt++) {
                int col = bn + warp_n * 32 + nt * 8 + (lane & 3) * 2;
                float* p0 = C + (size_t)row0 * OUTF + col;
                float* p1 = C + (size_t)(row0 + 8) * OUTF + col;
                float2 o0 = __ldcg((const float2*)p0);
                float2 o1 = __ldcg((const float2*)p1);
                o0.x += acc[mt][nt][0]; o0.y += acc[mt][nt][1];
                o1.x += acc[mt][nt][2]; o1.y += acc[mt][nt][3];
                *(float2*)p0 = o0;
                *(float2*)p1 = o1;
            }
        }
        __threadfence();
        __syncthreads();
        if (tid == 0) {
            if (kz == SPLITK - 1) atomicExch(&g_cnt[tile], 0u);
            else atomicAdd(&g_cnt[tile], 1u);
        }
    }
}

// ===========================================================================
typedef CUresult (*PFN_encode)(CUtensorMap*, CUtensorMapDataType, cuuint32_t,
                               void*, const cuuint64_t*, const cuuint64_t*,
                               const cuuint32_t*, const cuuint32_t*,
                               CUtensorMapInterleave, CUtensorMapSwizzle,
                               CUtensorMapL2promotion, CUtensorMapFloatOOBfill);

static CUtensorMap s_tma_a, s_tma_w;

static void make_map(PFN_encode enc, CUtensorMap* m, void* base, int rows) {
    cuuint64_t dims[2]    = {(cuuint64_t)K1, (cuuint64_t)rows};
    cuuint64_t strides[1] = {(cuuint64_t)K1 * 2};
    cuuint32_t box[2]     = {KTILE, 128};
    cuuint32_t estr[2]    = {1, 1};
    enc(m, CU_TENSOR_MAP_DATA_TYPE_FLOAT16, 2, base, dims, strides, box, estr,
        CU_TENSOR_MAP_INTERLEAVE_NONE, CU_TENSOR_MAP_SWIZZLE_128B,
        CU_TENSOR_MAP_L2_PROMOTION_L2_128B, CU_TENSOR_MAP_FLOAT_OOB_FILL_NONE);
}

extern "C" void kernel_launch(void* const* d_in, const int* in_sizes, int n_in,
                              void* d_out, int out_size) {
    const float* x    = (const float*)d_in[0];   // [4096,1024]
    const float* bw   = (const float*)d_in[1];   // [1024,1024]
    const float* bias = (const float*)d_in[2];   // [1024]
    const float* sw   = (const float*)d_in[3];   // [1024,1024,8]
    float* out = (float*)d_out;                  // [4096,1024]

    static bool inited = false;
    if (!inited) {
        void* fn = nullptr;
        cudaDriverEntryPointQueryResult st;
        cudaGetDriverEntryPointByVersion("cuTensorMapEncodeTiled", &fn, 12000,
                                         cudaEnableDefault, &st);
        PFN_encode enc = (PFN_encode)fn;
        void *pa = nullptr, *pw = nullptr;
        cudaGetSymbolAddress(&pa, g_A);
        cudaGetSymbolAddress(&pw, g_W);
        make_map(enc, &s_tma_a, pa, NMAT);
        make_map(enc, &s_tma_w, pw, OUTF);
        cudaFuncSetAttribute(gemm_kernel,
                             cudaFuncAttributeMaxDynamicSharedMemorySize, SMEM_TOTAL);
        inited = true;
    }

    build_A_kernel<<<(NMAT * INF + 255) / 256, 256>>>(x);
    pack_W_kernel<<<(OUTF * INF + 255) / 256, 256>>>(bw, sw);

    dim3 grid(OUTF / BN, NMAT / BM, SPLITK);   // (8, 32, 8) = 2048 CTAs
    gemm_kernel<<<grid, 256, SMEM_TOTAL>>>(s_tma_a, s_tma_w, bias, out);
}

// round 13
// speedup vs baseline: 1.0559x; 1.0559x over previous
#include <cuda_runtime.h>
#include <cuda.h>
#include <cuda_fp16.h>
#include <cstdint>
#include <math.h>

#define NMAT 4096
#define INF  1024
#define OUTF 1024
#define NB   8
#define K1   9216
#define KTILE 64                   // fp16 per k-chunk = 128 bytes (SW128 atom)
#define KCH (K1 / KTILE)           // 144
#define SPLITK 4
#define KT_PER (KCH / SPLITK)      // 36
#define BM 128
#define BN 128
#define STAGES 3
#define THREADS 128                // 4 warps, 2x2 grid of 64x64 warp tiles

#define TILE_BYTES (BM * 128)                  // 16384 per operand
#define STAGE_BYTES (2 * TILE_BYTES)           // 32768
#define SM_STAGE(s) (1024 + (s) * STAGE_BYTES)
#define SMEM_TOTAL (1024 + STAGES * STAGE_BYTES)   // 99328
#define NTILES 256

// ---------------- scratch (__device__ globals; no allocs allowed) ----------
__device__ __align__(128) __half g_A[(size_t)NMAT * K1];
__device__ __align__(128) __half g_W[(size_t)OUTF * K1];
__device__ unsigned g_cnt[NTILES];   // zero-init; self-resetting each run

// ---------------- PTX helpers (family-portable only: sm_90 class) ----------
__device__ __forceinline__ uint32_t smem_u32(const void* p) {
    uint32_t a;
    asm("{ .reg .u64 t; cvta.to.shared.u64 t, %1; cvt.u32.u64 %0, t; }" : "=r"(a) : "l"(p));
    return a;
}
#define MBAR_INIT(addr, cnt) \
    asm volatile("mbarrier.init.shared.b64 [%0], %1;" :: "r"(addr), "r"(cnt) : "memory")
#define MBAR_EXPECT_TX(addr, bytes) \
    asm volatile("mbarrier.arrive.expect_tx.shared.b64 _, [%0], %1;" :: "r"(addr), "r"(bytes) : "memory")
#define MBAR_WAIT(addr, ph) do {                                              \
    uint32_t _m = (addr); uint32_t _p = (ph); uint32_t _d;                    \
    asm volatile("{\n .reg .pred p;\n"                                        \
        " mbarrier.try_wait.parity.acquire.cta.shared::cta.b64 p, [%1], %2;\n"\
        " selp.b32 %0, 1, 0, p;\n}" : "=r"(_d) : "r"(_m), "r"(_p) : "memory");\
    if (!_d) {                                                                \
        asm volatile("{\n .reg .pred P1;\n"                                   \
            "W_%=:\n"                                                         \
            " mbarrier.try_wait.parity.acquire.cta.shared::cta.b64 P1, [%0], %1, 0x989680;\n" \
            " @P1 bra.uni D_%=;\n bra.uni W_%=;\nD_%=:\n}"                    \
            :: "r"(_m), "r"(_p) : "memory");                                  \
    }                                                                         \
} while (0)

__device__ __forceinline__ void tma_load_2d(uint32_t dst, const void* map,
                                            int cx, int cy, uint32_t mbar) {
    asm volatile(
        "cp.async.bulk.tensor.2d.shared::cta.global.tile.mbarrier::complete_tx::bytes "
        "[%0], [%1, {%2, %3}], [%4];"
        :: "r"(dst), "l"(map), "r"(cx), "r"(cy), "r"(mbar) : "memory");
}
__device__ __forceinline__ void ldsm_x4(uint32_t& r0, uint32_t& r1, uint32_t& r2,
                                        uint32_t& r3, uint32_t addr) {
    asm volatile("ldmatrix.sync.aligned.m8n8.x4.shared.b16 {%0,%1,%2,%3}, [%4];"
                 : "=r"(r0), "=r"(r1), "=r"(r2), "=r"(r3) : "r"(addr));
}
__device__ __forceinline__ void mma_f16(float& c0, float& c1, float& c2, float& c3,
                                        uint32_t a0, uint32_t a1, uint32_t a2, uint32_t a3,
                                        uint32_t b0, uint32_t b1) {
    asm volatile("mma.sync.aligned.m16n8k16.row.col.f32.f16.f16.f32 "
                 "{%0,%1,%2,%3}, {%4,%5,%6,%7}, {%8,%9}, {%0,%1,%2,%3};"
                 : "+f"(c0), "+f"(c1), "+f"(c2), "+f"(c3)
                 : "r"(a0), "r"(a1), "r"(a2), "r"(a3), "r"(b0), "r"(b1));
}

// ===========================================================================
// Stage 1: dense zero + 4-slot scatter (deterministic, single-thread writes)
// ===========================================================================
__global__ void build_A_kernel(const float* __restrict__ x) {
    int idx = blockIdx.x * blockDim.x + threadIdx.x;
    if (idx >= NMAT * INF) return;
    float v = x[idx];
    size_t rb = (size_t)(idx >> 10) * K1 + (idx & 1023);

    g_A[rb] = __float2half_rn(v / (1.0f + __expf(-v)));   // silu
    const __half hz = __float2half_rn(0.0f);
#pragma unroll
    for (int s = 1; s <= 8; s++) g_A[rb + s * 1024] = hz;

    float p = (v + 2.2f) * 2.5f;
    if (p >= 0.0f && p < 11.0f) {
        float pf = floorf(p);
        int iv = (int)pf;
        float u = p - pf;
        float u2 = u * u, u3 = u2 * u;
        const float i6 = 1.0f / 6.0f;
        float c0 = (-u3 + 3.0f * u2 - 3.0f * u + 1.0f) * i6;       // j = iv-3
        float c1 = (3.0f * u3 - 6.0f * u2 + 4.0f) * i6;            // j = iv-2
        float c2 = (-3.0f * u3 + 3.0f * u2 + 3.0f * u + 1.0f) * i6;// j = iv-1
        float c3 = u3 * i6;                                        // j = iv
        int j0 = iv - 3;
        if (j0 >= 0 && j0 < 8)         g_A[rb + (j0 + 1) * 1024] = __float2half_rn(c0);
        if (j0 + 1 >= 0 && j0 + 1 < 8) g_A[rb + (j0 + 2) * 1024] = __float2half_rn(c1);
        if (j0 + 2 >= 0 && j0 + 2 < 8) g_A[rb + (j0 + 3) * 1024] = __float2half_rn(c2);
        if (j0 + 3 >= 0 && j0 + 3 < 8) g_A[rb + (j0 + 4) * 1024] = __float2half_rn(c3);
    }
}

__global__ void pack_W_kernel(const float* __restrict__ bw,
                              const float* __restrict__ sw) {
    int idx = blockIdx.x * blockDim.x + threadIdx.x;
    if (idx >= OUTF * INF) return;
    size_t rb = (size_t)(idx >> 10) * K1 + (idx & 1023);
    g_W[rb] = __float2half_rn(bw[idx]);
    const float4* s4 = (const float4*)(sw + (size_t)idx * NB);
    float4 s0 = s4[0], s1 = s4[1];
    g_W[rb + 1 * 1024] = __float2half_rn(s0.x);
    g_W[rb + 2 * 1024] = __float2half_rn(s0.y);
    g_W[rb + 3 * 1024] = __float2half_rn(s0.z);
    g_W[rb + 4 * 1024] = __float2half_rn(s0.w);
    g_W[rb + 5 * 1024] = __float2half_rn(s1.x);
    g_W[rb + 6 * 1024] = __float2half_rn(s1.y);
    g_W[rb + 7 * 1024] = __float2half_rn(s1.z);
    g_W[rb + 8 * 1024] = __float2half_rn(s1.w);
}

// ===========================================================================
// GEMM: 128x128 tile, 4 warps (2x2 grid of 64x64 warp tiles), TMA + mbarrier
// pipeline (3 stages, prefetch 2), serial split-K 4
// ===========================================================================
__global__ void __launch_bounds__(THREADS, 2)
gemm_kernel(const __grid_constant__ CUtensorMap tma_a,
            const __grid_constant__ CUtensorMap tma_w,
            const float* __restrict__ bias, float* __restrict__ C) {
    extern __shared__ __align__(1024) char smem[];
    uint32_t sb = smem_u32(smem);

    const int tid = threadIdx.x;
    const int wid = tid >> 5;
    const int lane = tid & 31;
    const int warp_m = wid & 1;        // 2 warps along M (64 each)
    const int warp_n = wid >> 1;       // 2 warps along N (64 each)
    const int bm = blockIdx.y * BM;
    const int bn = blockIdx.x * BN;
    const int kz = blockIdx.z;
    const int kb0 = kz * KT_PER;
    const int tile = blockIdx.y * gridDim.x + blockIdx.x;

    if (tid == 0) {
#pragma unroll
        for (int s = 0; s < STAGES; s++) MBAR_INIT(sb + s * 8, 1);
    }
    __syncthreads();

    if (tid == 0) {
#pragma unroll
        for (int j = 0; j < 2; j++) {
            uint32_t st = sb + SM_STAGE(j);
            MBAR_EXPECT_TX(sb + j * 8, STAGE_BYTES);
            tma_load_2d(st,              &tma_a, (kb0 + j) * KTILE, bm, sb + j * 8);
            tma_load_2d(st + TILE_BYTES, &tma_w, (kb0 + j) * KTILE, bn, sb + j * 8);
        }
    }

    float acc[4][8][4];                // [mt][nt][frag] : 64x64 warp tile
#pragma unroll
    for (int i = 0; i < 4; i++)
#pragma unroll
        for (int j = 0; j < 8; j++)
#pragma unroll
            for (int q = 0; q < 4; q++) acc[i][j][q] = 0.0f;

    const int a_row = lane & 15;
    const int a_c16 = (lane >> 4) << 4;
    const int b_row = ((lane >> 4) << 3) + (lane & 7);
    const int b_c16 = ((lane >> 3) & 1) << 4;

    for (int j = 0; j < KT_PER; j++) {
        int s = j % STAGES;
        MBAR_WAIT(sb + s * 8, (j / STAGES) & 1);
        __syncthreads();   // all threads done reading stage (j+2)%3 before refill
        if (tid == 0 && j + 2 < KT_PER) {
            int jn = j + 2, sn = jn % STAGES;
            uint32_t st = sb + SM_STAGE(sn);
            MBAR_EXPECT_TX(sb + sn * 8, STAGE_BYTES);
            tma_load_2d(st,              &tma_a, (kb0 + jn) * KTILE, bm, sb + sn * 8);
            tma_load_2d(st + TILE_BYTES, &tma_w, (kb0 + jn) * KTILE, bn, sb + sn * 8);
        }

        uint32_t sA = sb + SM_STAGE(s);
        uint32_t sB = sA + TILE_BYTES;
#pragma unroll
        for (int kk = 0; kk < 4; kk++) {
            int k0b = kk * 32;
            uint32_t a[4][4];
#pragma unroll
            for (int mt = 0; mt < 4; mt++) {
                int row = warp_m * 64 + mt * 16 + a_row;
                uint32_t off = row * 128 + ((k0b + a_c16) ^ ((row & 7) << 4));
                ldsm_x4(a[mt][0], a[mt][1], a[mt][2], a[mt][3], sA + off);
            }
            uint32_t bf[8][2];
#pragma unroll
            for (int pq = 0; pq < 4; pq++) {   // paired x4: 2 n-tiles per LDSM
                int row = warp_n * 64 + pq * 16 + b_row;
                uint32_t off = row * 128 + ((k0b + b_c16) ^ ((row & 7) << 4));
                ldsm_x4(bf[2 * pq][0], bf[2 * pq][1], bf[2 * pq + 1][0], bf[2 * pq + 1][1],
                        sB + off);
            }
#pragma unroll
            for (int mt = 0; mt < 4; mt++)
#pragma unroll
                for (int nt = 0; nt < 8; nt++)
                    mma_f16(acc[mt][nt][0], acc[mt][nt][1], acc[mt][nt][2], acc[mt][nt][3],
                            a[mt][0], a[mt][1], a[mt][2], a[mt][3],
                            bf[nt][0], bf[nt][1]);
        }
    }

    // ---------------- serial split-K epilogue (self-resetting counters) ----
    if (kz == 0) {
#pragma unroll
        for (int mt = 0; mt < 4; mt++) {
            int row0 = bm + warp_m * 64 + mt * 16 + (lane >> 2);
#pragma unroll
            for (int nt = 0; nt < 8; nt++) {
                int col = bn + warp_n * 64 + nt * 8 + (lane & 3) * 2;
                float b0 = __ldg(bias + col);
                float b1 = __ldg(bias + col + 1);
                float2 v0 = make_float2(acc[mt][nt][0] + b0, acc[mt][nt][1] + b1);
                float2 v1 = make_float2(acc[mt][nt][2] + b0, acc[mt][nt][3] + b1);
                *(float2*)(C + (size_t)row0 * OUTF + col)       = v0;
                *(float2*)(C + (size_t)(row0 + 8) * OUTF + col) = v1;
            }
        }
        __threadfence();
        __syncthreads();
        if (tid == 0) atomicAdd(&g_cnt[tile], 1u);
    } else {
        if (tid == 0) {
            while (atomicAdd(&g_cnt[tile], 0u) < (unsigned)kz) __nanosleep(64);
        }
        __syncthreads();
        __threadfence();
#pragma unroll
        for (int mt = 0; mt < 4; mt++) {
            int row0 = bm + warp_m * 64 + mt * 16 + (lane >> 2);
#pragma unroll
            for (int nt = 0; nt < 8; nt++) {
                int col = bn + warp_n * 64 + nt * 8 + (lane & 3) * 2;
                float* p0 = C + (size_t)row0 * OUTF + col;
                float* p1 = C + (size_t)(row0 + 8) * OUTF + col;
                float2 o0 = __ldcg((const float2*)p0);
                float2 o1 = __ldcg((const float2*)p1);
                o0.x += acc[mt][nt][0]; o0.y += acc[mt][nt][1];
                o1.x += acc[mt][nt][2]; o1.y += acc[mt][nt][3];
                *(float2*)p0 = o0;
                *(float2*)p1 = o1;
            }
        }
        __threadfence();
        __syncthreads();
        if (tid == 0) {
            if (kz == SPLITK - 1) atomicExch(&g_cnt[tile], 0u);
            else atomicAdd(&g_cnt[tile], 1u);
        }
    }
}

// ===========================================================================
typedef CUresult (*PFN_encode)(CUtensorMap*, CUtensorMapDataType, cuuint32_t,
                               void*, const cuuint64_t*, const cuuint64_t*,
                               const cuuint32_t*, const cuuint32_t*,
                               CUtensorMapInterleave, CUtensorMapSwizzle,
                               CUtensorMapL2promotion, CUtensorMapFloatOOBfill);

static CUtensorMap s_tma_a, s_tma_w;

static void make_map(PFN_encode enc, CUtensorMap* m, void* base, int rows) {
    cuuint64_t dims[2]    = {(cuuint64_t)K1, (cuuint64_t)rows};
    cuuint64_t strides[1] = {(cuuint64_t)K1 * 2};
    cuuint32_t box[2]     = {KTILE, 128};
    cuuint32_t estr[2]    = {1, 1};
    enc(m, CU_TENSOR_MAP_DATA_TYPE_FLOAT16, 2, base, dims, strides, box, estr,
        CU_TENSOR_MAP_INTERLEAVE_NONE, CU_TENSOR_MAP_SWIZZLE_128B,
        CU_TENSOR_MAP_L2_PROMOTION_L2_128B, CU_TENSOR_MAP_FLOAT_OOB_FILL_NONE);
}

extern "C" void kernel_launch(void* const* d_in, const int* in_sizes, int n_in,
                              void* d_out, int out_size) {
    const float* x    = (const float*)d_in[0];   // [4096,1024]
    const float* bw   = (const float*)d_in[1];   // [1024,1024]
    const float* bias = (const float*)d_in[2];   // [1024]
    const float* sw   = (const float*)d_in[3];   // [1024,1024,8]
    float* out = (float*)d_out;                  // [4096,1024]

    static bool inited = false;
    if (!inited) {
        void* fn = nullptr;
        cudaDriverEntryPointQueryResult st;
        cudaGetDriverEntryPointByVersion("cuTensorMapEncodeTiled", &fn, 12000,
                                         cudaEnableDefault, &st);
        PFN_encode enc = (PFN_encode)fn;
        void *pa = nullptr, *pw = nullptr;
        cudaGetSymbolAddress(&pa, g_A);
        cudaGetSymbolAddress(&pw, g_W);
        make_map(enc, &s_tma_a, pa, NMAT);
        make_map(enc, &s_tma_w, pw, OUTF);
        cudaFuncSetAttribute(gemm_kernel,
                             cudaFuncAttributeMaxDynamicSharedMemorySize, SMEM_TOTAL);
        inited = true;
    }

    build_A_kernel<<<(NMAT * INF + 255) / 256, 256>>>(x);
    pack_W_kernel<<<(OUTF * INF + 255) / 256, 256>>>(bw, sw);

    dim3 grid(OUTF / BN, NMAT / BM, SPLITK);   // (8, 32, 4) = 1024 CTAs
    gemm_kernel<<<grid, THREADS, SMEM_TOTAL>>>(s_tma_a, s_tma_w, bias, out);
}

// round 14
// speedup vs baseline: 1.1028x; 1.0444x over previous
#include <cuda_runtime.h>
#include <cuda.h>
#include <cuda_fp16.h>
#include <cstdint>
#include <math.h>

#define NMAT 4096
#define INF  1024
#define OUTF 1024
#define NB   8
#define K1   9216
#define KTILE 64                   // fp16 per k-chunk = 128 bytes (SW128 atom)
#define KCH (K1 / KTILE)           // 144
#define SPLITK 4
#define KT_PER (KCH / SPLITK)      // 36
#define BM 128
#define BN 128
#define STAGES 3
#define THREADS 128                // 4 warps, 2x2 grid of 64x64 warp tiles

#define TILE_BYTES (BM * 128)                  // 16384 per operand
#define STAGE_BYTES (2 * TILE_BYTES)           // 32768
#define SM_STAGE(s) (1024 + (s) * STAGE_BYTES)
#define SMEM_TOTAL (1024 + STAGES * STAGE_BYTES)   // 99328
#define NTILES 256

#define BLK_A (NMAT * INF / 256)       // 16384 blocks for build_A
#define BLK_W (OUTF * INF / 2 / 256)   // 2048 blocks for pack_W (2 elems/thread)

// ---------------- scratch (__device__ globals; no allocs allowed) ----------
__device__ __align__(128) __half g_A[(size_t)NMAT * K1];
__device__ __align__(128) __half g_W[(size_t)OUTF * K1];
__device__ unsigned g_cnt[NTILES];   // zero-init; self-resetting each run

// ---------------- PTX helpers (family-portable only: sm_90 class) ----------
__device__ __forceinline__ uint32_t smem_u32(const void* p) {
    uint32_t a;
    asm("{ .reg .u64 t; cvta.to.shared.u64 t, %1; cvt.u32.u64 %0, t; }" : "=r"(a) : "l"(p));
    return a;
}
#define MBAR_INIT(addr, cnt) \
    asm volatile("mbarrier.init.shared.b64 [%0], %1;" :: "r"(addr), "r"(cnt) : "memory")
#define MBAR_EXPECT_TX(addr, bytes) \
    asm volatile("mbarrier.arrive.expect_tx.shared.b64 _, [%0], %1;" :: "r"(addr), "r"(bytes) : "memory")
#define MBAR_WAIT(addr, ph) do {                                              \
    uint32_t _m = (addr); uint32_t _p = (ph); uint32_t _d;                    \
    asm volatile("{\n .reg .pred p;\n"                                        \
        " mbarrier.try_wait.parity.acquire.cta.shared::cta.b64 p, [%1], %2;\n"\
        " selp.b32 %0, 1, 0, p;\n}" : "=r"(_d) : "r"(_m), "r"(_p) : "memory");\
    if (!_d) {                                                                \
        asm volatile("{\n .reg .pred P1;\n"                                   \
            "W_%=:\n"                                                         \
            " mbarrier.try_wait.parity.acquire.cta.shared::cta.b64 P1, [%0], %1, 0x989680;\n" \
            " @P1 bra.uni D_%=;\n bra.uni W_%=;\nD_%=:\n}"                    \
            :: "r"(_m), "r"(_p) : "memory");                                  \
    }                                                                         \
} while (0)

__device__ __forceinline__ void tma_load_2d(uint32_t dst, const void* map,
                                            int cx, int cy, uint32_t mbar) {
    asm volatile(
        "cp.async.bulk.tensor.2d.shared::cta.global.tile.mbarrier::complete_tx::bytes "
        "[%0], [%1, {%2, %3}], [%4];"
        :: "r"(dst), "l"(map), "r"(cx), "r"(cy), "r"(mbar) : "memory");
}
__device__ __forceinline__ void ldsm_x4(uint32_t& r0, uint32_t& r1, uint32_t& r2,
                                        uint32_t& r3, uint32_t addr) {
    asm volatile("ldmatrix.sync.aligned.m8n8.x4.shared.b16 {%0,%1,%2,%3}, [%4];"
                 : "=r"(r0), "=r"(r1), "=r"(r2), "=r"(r3) : "r"(addr));
}
__device__ __forceinline__ void mma_f16(float& c0, float& c1, float& c2, float& c3,
                                        uint32_t a0, uint32_t a1, uint32_t a2, uint32_t a3,
                                        uint32_t b0, uint32_t b1) {
    asm volatile("mma.sync.aligned.m16n8k16.row.col.f32.f16.f16.f32 "
                 "{%0,%1,%2,%3}, {%4,%5,%6,%7}, {%8,%9}, {%0,%1,%2,%3};"
                 : "+f"(c0), "+f"(c1), "+f"(c2), "+f"(c3)
                 : "r"(a0), "r"(a1), "r"(a2), "r"(a3), "r"(b0), "r"(b1));
}

// ===========================================================================
// Fused prep: blocks [0, BLK_A) build A (R6-proven Cox-de Boor lattice),
//             blocks [BLK_A, BLK_A+BLK_W) pack W (half2 stores)
// ===========================================================================
__global__ void prep_kernel(const float* __restrict__ x,
                            const float* __restrict__ bw,
                            const float* __restrict__ sw) {
    int blk = blockIdx.x;
    if (blk < BLK_A) {
        // ----- build_A: one element per thread, Cox-de Boor lattice -----
        int idx = blk * 256 + threadIdx.x;
        float v = x[idx];

        float vals[9];
        vals[0] = v / (1.0f + __expf(-v));   // SiLU

        const float h = 0.4f, lo = -1.0f;
        float b[11];
#pragma unroll
        for (int j = 0; j < 11; j++) {
            float t0 = (float)(j - 3) * h + lo;
            float t1 = (float)(j - 2) * h + lo;
            b[j] = (v >= t0 && v < t1) ? 1.0f : 0.0f;
        }
#pragma unroll
        for (int k = 1; k <= 3; k++) {
            float inv = 1.0f / ((float)k * h + 1e-8f);
#pragma unroll
            for (int j = 0; j + k < 11; j++) {
                float tj   = (float)(j - 3) * h + lo;
                float tjk1 = (float)(j + k - 2) * h + lo;
                b[j] = (v - tj) * inv * b[j] + (tjk1 - v) * inv * b[j + 1];
            }
        }
#pragma unroll
        for (int j = 0; j < NB; j++) vals[1 + j] = b[j];

        size_t rb = (size_t)(idx >> 10) * K1 + (idx & 1023);
#pragma unroll
        for (int s = 0; s < 9; s++)
            g_A[rb + s * 1024] = __float2half_rn(vals[s]);
    } else {
        // ----- pack_W: two adjacent i per thread, half2 stores -----
        int idx2 = (blk - BLK_A) * 256 + threadIdx.x;
        int o = idx2 >> 9;
        int i = (idx2 & 511) * 2;
        size_t rb = (size_t)o * K1 + i;

        float2 b2 = ((const float2*)bw)[idx2];
        *(__half2*)(g_W + rb) = __floats2half2_rn(b2.x, b2.y);

        const float4* s4 = (const float4*)(sw + ((size_t)o * INF + i) * NB);
        float4 p0 = s4[0], p1 = s4[1], q0 = s4[2], q1 = s4[3];
        float a0[8] = {p0.x, p0.y, p0.z, p0.w, p1.x, p1.y, p1.z, p1.w};
        float a1[8] = {q0.x, q0.y, q0.z, q0.w, q1.x, q1.y, q1.z, q1.w};
#pragma unroll
        for (int j = 0; j < NB; j++)
            *(__half2*)(g_W + rb + (size_t)(j + 1) * 1024) =
                __floats2half2_rn(a0[j], a1[j]);
    }
}

// ===========================================================================
// GEMM: 128x128 tile, 4 warps (2x2 grid of 64x64 warp tiles), TMA + mbarrier
// pipeline (3 stages, prefetch 2), serial split-K 4   [R13 frozen]
// ===========================================================================
__global__ void __launch_bounds__(THREADS, 2)
gemm_kernel(const __grid_constant__ CUtensorMap tma_a,
            const __grid_constant__ CUtensorMap tma_w,
            const float* __restrict__ bias, float* __restrict__ C) {
    extern __shared__ __align__(1024) char smem[];
    uint32_t sb = smem_u32(smem);

    const int tid = threadIdx.x;
    const int wid = tid >> 5;
    const int lane = tid & 31;
    const int warp_m = wid & 1;
    const int warp_n = wid >> 1;
    const int bm = blockIdx.y * BM;
    const int bn = blockIdx.x * BN;
    const int kz = blockIdx.z;
    const int kb0 = kz * KT_PER;
    const int tile = blockIdx.y * gridDim.x + blockIdx.x;

    if (tid == 0) {
#pragma unroll
        for (int s = 0; s < STAGES; s++) MBAR_INIT(sb + s * 8, 1);
    }
    __syncthreads();

    if (tid == 0) {
#pragma unroll
        for (int j = 0; j < 2; j++) {
            uint32_t st = sb + SM_STAGE(j);
            MBAR_EXPECT_TX(sb + j * 8, STAGE_BYTES);
            tma_load_2d(st,              &tma_a, (kb0 + j) * KTILE, bm, sb + j * 8);
            tma_load_2d(st + TILE_BYTES, &tma_w, (kb0 + j) * KTILE, bn, sb + j * 8);
        }
    }

    float acc[4][8][4];
#pragma unroll
    for (int i = 0; i < 4; i++)
#pragma unroll
        for (int j = 0; j < 8; j++)
#pragma unroll
            for (int q = 0; q < 4; q++) acc[i][j][q] = 0.0f;

    const int a_row = lane & 15;
    const int a_c16 = (lane >> 4) << 4;
    const int b_row = ((lane >> 4) << 3) + (lane & 7);
    const int b_c16 = ((lane >> 3) & 1) << 4;

    for (int j = 0; j < KT_PER; j++) {
        int s = j % STAGES;
        MBAR_WAIT(sb + s * 8, (j / STAGES) & 1);
        __syncthreads();
        if (tid == 0 && j + 2 < KT_PER) {
            int jn = j + 2, sn = jn % STAGES;
            uint32_t st = sb + SM_STAGE(sn);
            MBAR_EXPECT_TX(sb + sn * 8, STAGE_BYTES);
            tma_load_2d(st,              &tma_a, (kb0 + jn) * KTILE, bm, sb + sn * 8);
            tma_load_2d(st + TILE_BYTES, &tma_w, (kb0 + jn) * KTILE, bn, sb + sn * 8);
        }

        uint32_t sA = sb + SM_STAGE(s);
        uint32_t sB = sA + TILE_BYTES;
#pragma unroll
        for (int kk = 0; kk < 4; kk++) {
            int k0b = kk * 32;
            uint32_t a[4][4];
#pragma unroll
            for (int mt = 0; mt < 4; mt++) {
                int row = warp_m * 64 + mt * 16 + a_row;
                uint32_t off = row * 128 + ((k0b + a_c16) ^ ((row & 7) << 4));
                ldsm_x4(a[mt][0], a[mt][1], a[mt][2], a[mt][3], sA + off);
            }
            uint32_t bf[8][2];
#pragma unroll
            for (int pq = 0; pq < 4; pq++) {
                int row = warp_n * 64 + pq * 16 + b_row;
                uint32_t off = row * 128 + ((k0b + b_c16) ^ ((row & 7) << 4));
                ldsm_x4(bf[2 * pq][0], bf[2 * pq][1], bf[2 * pq + 1][0], bf[2 * pq + 1][1],
                        sB + off);
            }
#pragma unroll
            for (int mt = 0; mt < 4; mt++)
#pragma unroll
                for (int nt = 0; nt < 8; nt++)
                    mma_f16(acc[mt][nt][0], acc[mt][nt][1], acc[mt][nt][2], acc[mt][nt][3],
                            a[mt][0], a[mt][1], a[mt][2], a[mt][3],
                            bf[nt][0], bf[nt][1]);
        }
    }

    // ---------------- serial split-K epilogue (self-resetting counters) ----
    if (kz == 0) {
#pragma unroll
        for (int mt = 0; mt < 4; mt++) {
            int row0 = bm + warp_m * 64 + mt * 16 + (lane >> 2);
#pragma unroll
            for (int nt = 0; nt < 8; nt++) {
                int col = bn + warp_n * 64 + nt * 8 + (lane & 3) * 2;
                float b0 = __ldg(bias + col);
                float b1 = __ldg(bias + col + 1);
                float2 v0 = make_float2(acc[mt][nt][0] + b0, acc[mt][nt][1] + b1);
                float2 v1 = make_float2(acc[mt][nt][2] + b0, acc[mt][nt][3] + b1);
                *(float2*)(C + (size_t)row0 * OUTF + col)       = v0;
                *(float2*)(C + (size_t)(row0 + 8) * OUTF + col) = v1;
            }
        }
        __threadfence();
        __syncthreads();
        if (tid == 0) atomicAdd(&g_cnt[tile], 1u);
    } else {
        if (tid == 0) {
            while (atomicAdd(&g_cnt[tile], 0u) < (unsigned)kz) __nanosleep(64);
        }
        __syncthreads();
        __threadfence();
#pragma unroll
        for (int mt = 0; mt < 4; mt++) {
            int row0 = bm + warp_m * 64 + mt * 16 + (lane >> 2);
#pragma unroll
            for (int nt = 0; nt < 8; nt++) {
                int col = bn + warp_n * 64 + nt * 8 + (lane & 3) * 2;
                float* p0 = C + (size_t)row0 * OUTF + col;
                float* p1 = C + (size_t)(row0 + 8) * OUTF + col;
                float2 o0 = __ldcg((const float2*)p0);
                float2 o1 = __ldcg((const float2*)p1);
                o0.x += acc[mt][nt][0]; o0.y += acc[mt][nt][1];
                o1.x += acc[mt][nt][2]; o1.y += acc[mt][nt][3];
                *(float2*)p0 = o0;
                *(float2*)p1 = o1;
            }
        }
        __threadfence();
        __syncthreads();
        if (tid == 0) {
            if (kz == SPLITK - 1) atomicExch(&g_cnt[tile], 0u);
            else atomicAdd(&g_cnt[tile], 1u);
        }
    }
}

// ===========================================================================
typedef CUresult (*PFN_encode)(CUtensorMap*, CUtensorMapDataType, cuuint32_t,
                               void*, const cuuint64_t*, const cuuint64_t*,
                               const cuuint32_t*, const cuuint32_t*,
                               CUtensorMapInterleave, CUtensorMapSwizzle,
                               CUtensorMapL2promotion, CUtensorMapFloatOOBfill);

static CUtensorMap s_tma_a, s_tma_w;

static void make_map(PFN_encode enc, CUtensorMap* m, void* base, int rows) {
    cuuint64_t dims[2]    = {(cuuint64_t)K1, (cuuint64_t)rows};
    cuuint64_t strides[1] = {(cuuint64_t)K1 * 2};
    cuuint32_t box[2]     = {KTILE, 128};
    cuuint32_t estr[2]    = {1, 1};
    enc(m, CU_TENSOR_MAP_DATA_TYPE_FLOAT16, 2, base, dims, strides, box, estr,
        CU_TENSOR_MAP_INTERLEAVE_NONE, CU_TENSOR_MAP_SWIZZLE_128B,
        CU_TENSOR_MAP_L2_PROMOTION_L2_128B, CU_TENSOR_MAP_FLOAT_OOB_FILL_NONE);
}

extern "C" void kernel_launch(void* const* d_in, const int* in_sizes, int n_in,
                              void* d_out, int out_size) {
    const float* x    = (const float*)d_in[0];   // [4096,1024]
    const float* bw   = (const float*)d_in[1];   // [1024,1024]
    const float* bias = (const float*)d_in[2];   // [1024]
    const float* sw   = (const float*)d_in[3];   // [1024,1024,8]
    float* out = (float*)d_out;                  // [4096,1024]

    static bool inited = false;
    if (!inited) {
        void* fn = nullptr;
        cudaDriverEntryPointQueryResult st;
        cudaGetDriverEntryPointByVersion("cuTensorMapEncodeTiled", &fn, 12000,
                                         cudaEnableDefault, &st);
        PFN_encode enc = (PFN_encode)fn;
        void *pa = nullptr, *pw = nullptr;
        cudaGetSymbolAddress(&pa, g_A);
        cudaGetSymbolAddress(&pw, g_W);
        make_map(enc, &s_tma_a, pa, NMAT);
        make_map(enc, &s_tma_w, pw, OUTF);
        cudaFuncSetAttribute(gemm_kernel,
                             cudaFuncAttributeMaxDynamicSharedMemorySize, SMEM_TOTAL);
        inited = true;
    }

    prep_kernel<<<BLK_A + BLK_W, 256>>>(x, bw, sw);

    dim3 grid(OUTF / BN, NMAT / BM, SPLITK);   // (8, 32, 4) = 1024 CTAs
    gemm_kernel<<<grid, THREADS, SMEM_TOTAL>>>(s_tma_a, s_tma_w, bias, out);
}

// round 15
// speedup vs baseline: 1.1212x; 1.0167x over previous
#include <cuda_runtime.h>
#include <cuda.h>
#include <cuda_fp16.h>
#include <cstdint>
#include <math.h>

#define NMAT 4096
#define INF  1024
#define OUTF 1024
#define NB   8
#define K1   9216
#define KTILE 64                   // fp16 per k-chunk = 128 bytes (SW128 atom)
#define KCH (K1 / KTILE)           // 144
#define SPLITK 4
#define KT_PER (KCH / SPLITK)      // 36
#define BM 128
#define BN 128
#define STAGES 3
#define THREADS 256                // 8 warps, 2x4 grid of 64x32 warp tiles

#define TILE_BYTES (BM * 128)                  // 16384 per operand
#define STAGE_BYTES (2 * TILE_BYTES)           // 32768
#define SM_STAGE(s) (1024 + (s) * STAGE_BYTES)
#define SMEM_TOTAL (1024 + STAGES * STAGE_BYTES)   // 99328
#define NTILES 256

#define BLK_A (NMAT * INF / 256)       // 16384 blocks for build_A
#define BLK_W (OUTF * INF / 2 / 256)   // 2048 blocks for pack_W (2 elems/thread)

// ---------------- scratch (__device__ globals; no allocs allowed) ----------
__device__ __align__(128) __half g_A[(size_t)NMAT * K1];
__device__ __align__(128) __half g_W[(size_t)OUTF * K1];
__device__ unsigned g_cnt[NTILES];   // zero-init; self-resetting each run

// ---------------- PTX helpers (family-portable only: sm_90 class) ----------
__device__ __forceinline__ uint32_t smem_u32(const void* p) {
    uint32_t a;
    asm("{ .reg .u64 t; cvta.to.shared.u64 t, %1; cvt.u32.u64 %0, t; }" : "=r"(a) : "l"(p));
    return a;
}
#define MBAR_INIT(addr, cnt) \
    asm volatile("mbarrier.init.shared.b64 [%0], %1;" :: "r"(addr), "r"(cnt) : "memory")
#define MBAR_EXPECT_TX(addr, bytes) \
    asm volatile("mbarrier.arrive.expect_tx.shared.b64 _, [%0], %1;" :: "r"(addr), "r"(bytes) : "memory")
#define MBAR_WAIT(addr, ph) do {                                              \
    uint32_t _m = (addr); uint32_t _p = (ph); uint32_t _d;                    \
    asm volatile("{\n .reg .pred p;\n"                                        \
        " mbarrier.try_wait.parity.acquire.cta.shared::cta.b64 p, [%1], %2;\n"\
        " selp.b32 %0, 1, 0, p;\n}" : "=r"(_d) : "r"(_m), "r"(_p) : "memory");\
    if (!_d) {                                                                \
        asm volatile("{\n .reg .pred P1;\n"                                   \
            "W_%=:\n"                                                         \
            " mbarrier.try_wait.parity.acquire.cta.shared::cta.b64 P1, [%0], %1, 0x989680;\n" \
            " @P1 bra.uni D_%=;\n bra.uni W_%=;\nD_%=:\n}"                    \
            :: "r"(_m), "r"(_p) : "memory");                                  \
    }                                                                         \
} while (0)

__device__ __forceinline__ void tma_load_2d(uint32_t dst, const void* map,
                                            int cx, int cy, uint32_t mbar) {
    asm volatile(
        "cp.async.bulk.tensor.2d.shared::cta.global.tile.mbarrier::complete_tx::bytes "
        "[%0], [%1, {%2, %3}], [%4];"
        :: "r"(dst), "l"(map), "r"(cx), "r"(cy), "r"(mbar) : "memory");
}
__device__ __forceinline__ void ldsm_x4(uint32_t& r0, uint32_t& r1, uint32_t& r2,
                                        uint32_t& r3, uint32_t addr) {
    asm volatile("ldmatrix.sync.aligned.m8n8.x4.shared.b16 {%0,%1,%2,%3}, [%4];"
                 : "=r"(r0), "=r"(r1), "=r"(r2), "=r"(r3) : "r"(addr));
}
__device__ __forceinline__ void mma_f16(float& c0, float& c1, float& c2, float& c3,
                                        uint32_t a0, uint32_t a1, uint32_t a2, uint32_t a3,
                                        uint32_t b0, uint32_t b1) {
    asm volatile("mma.sync.aligned.m16n8k16.row.col.f32.f16.f16.f32 "
                 "{%0,%1,%2,%3}, {%4,%5,%6,%7}, {%8,%9}, {%0,%1,%2,%3};"
                 : "+f"(c0), "+f"(c1), "+f"(c2), "+f"(c3)
                 : "r"(a0), "r"(a1), "r"(a2), "r"(a3), "r"(b0), "r"(b1));
}

// ===========================================================================
// Fused prep: blocks [0, BLK_A) build A (Cox-de Boor lattice, R6-proven),
//             blocks [BLK_A, BLK_A+BLK_W) pack W (half2 stores)
// ===========================================================================
__global__ void prep_kernel(const float* __restrict__ x,
                            const float* __restrict__ bw,
                            const float* __restrict__ sw) {
    int blk = blockIdx.x;
    if (blk < BLK_A) {
        int idx = blk * 256 + threadIdx.x;
        float v = x[idx];

        float vals[9];
        vals[0] = v / (1.0f + __expf(-v));   // SiLU

        const float h = 0.4f, lo = -1.0f;
        float b[11];
#pragma unroll
        for (int j = 0; j < 11; j++) {
            float t0 = (float)(j - 3) * h + lo;
            float t1 = (float)(j - 2) * h + lo;
            b[j] = (v >= t0 && v < t1) ? 1.0f : 0.0f;
        }
#pragma unroll
        for (int k = 1; k <= 3; k++) {
            float inv = 1.0f / ((float)k * h + 1e-8f);
#pragma unroll
            for (int j = 0; j + k < 11; j++) {
                float tj   = (float)(j - 3) * h + lo;
                float tjk1 = (float)(j + k - 2) * h + lo;
                b[j] = (v - tj) * inv * b[j] + (tjk1 - v) * inv * b[j + 1];
            }
        }
#pragma unroll
        for (int j = 0; j < NB; j++) vals[1 + j] = b[j];

        size_t rb = (size_t)(idx >> 10) * K1 + (idx & 1023);
#pragma unroll
        for (int s = 0; s < 9; s++)
            g_A[rb + s * 1024] = __float2half_rn(vals[s]);
    } else {
        int idx2 = (blk - BLK_A) * 256 + threadIdx.x;
        int o = idx2 >> 9;
        int i = (idx2 & 511) * 2;
        size_t rb = (size_t)o * K1 + i;

        float2 b2 = ((const float2*)bw)[idx2];
        *(__half2*)(g_W + rb) = __floats2half2_rn(b2.x, b2.y);

        const float4* s4 = (const float4*)(sw + ((size_t)o * INF + i) * NB);
        float4 p0 = s4[0], p1 = s4[1], q0 = s4[2], q1 = s4[3];
        float a0[8] = {p0.x, p0.y, p0.z, p0.w, p1.x, p1.y, p1.z, p1.w};
        float a1[8] = {q0.x, q0.y, q0.z, q0.w, q1.x, q1.y, q1.z, q1.w};
#pragma unroll
        for (int j = 0; j < NB; j++)
            *(__half2*)(g_W + rb + (size_t)(j + 1) * 1024) =
                __floats2half2_rn(a0[j], a1[j]);
    }
}

// ===========================================================================
// GEMM: 128x128 tile, 8 warps (2x4 grid of 64x32 warp tiles), TMA + mbarrier
// pipeline (3 stages, prefetch 2), serial split-K 4   [R10-measured fastest]
// ===========================================================================
__global__ void __launch_bounds__(THREADS, 2)
gemm_kernel(const __grid_constant__ CUtensorMap tma_a,
            const __grid_constant__ CUtensorMap tma_w,
            const float* __restrict__ bias, float* __restrict__ C) {
    extern __shared__ __align__(1024) char smem[];
    uint32_t sb = smem_u32(smem);

    const int tid = threadIdx.x;
    const int wid = tid >> 5;
    const int lane = tid & 31;
    const int warp_m = wid & 1;        // 2 warps along M (64 each)
    const int warp_n = wid >> 1;       // 4 warps along N (32 each)
    const int bm = blockIdx.y * BM;
    const int bn = blockIdx.x * BN;
    const int kz = blockIdx.z;
    const int kb0 = kz * KT_PER;
    const int tile = blockIdx.y * gridDim.x + blockIdx.x;

    if (tid == 0) {
#pragma unroll
        for (int s = 0; s < STAGES; s++) MBAR_INIT(sb + s * 8, 1);
    }
    __syncthreads();

    if (tid == 0) {
#pragma unroll
        for (int j = 0; j < 2; j++) {
            uint32_t st = sb + SM_STAGE(j);
            MBAR_EXPECT_TX(sb + j * 8, STAGE_BYTES);
            tma_load_2d(st,              &tma_a, (kb0 + j) * KTILE, bm, sb + j * 8);
            tma_load_2d(st + TILE_BYTES, &tma_w, (kb0 + j) * KTILE, bn, sb + j * 8);
        }
    }

    float acc[4][4][4];
#pragma unroll
    for (int i = 0; i < 4; i++)
#pragma unroll
        for (int j = 0; j < 4; j++)
#pragma unroll
            for (int q = 0; q < 4; q++) acc[i][j][q] = 0.0f;

    const int a_row = lane & 15;
    const int a_c16 = (lane >> 4) << 4;
    const int b_row = ((lane >> 4) << 3) + (lane & 7);
    const int b_c16 = ((lane >> 3) & 1) << 4;

    for (int j = 0; j < KT_PER; j++) {
        int s = j % STAGES;
        MBAR_WAIT(sb + s * 8, (j / STAGES) & 1);
        __syncthreads();
        if (tid == 0 && j + 2 < KT_PER) {
            int jn = j + 2, sn = jn % STAGES;
            uint32_t st = sb + SM_STAGE(sn);
            MBAR_EXPECT_TX(sb + sn * 8, STAGE_BYTES);
            tma_load_2d(st,              &tma_a, (kb0 + jn) * KTILE, bm, sb + sn * 8);
            tma_load_2d(st + TILE_BYTES, &tma_w, (kb0 + jn) * KTILE, bn, sb + sn * 8);
        }

        uint32_t sA = sb + SM_STAGE(s);
        uint32_t sB = sA + TILE_BYTES;
#pragma unroll
        for (int kk = 0; kk < 4; kk++) {
            int k0b = kk * 32;
            uint32_t a[4][4];
#pragma unroll
            for (int mt = 0; mt < 4; mt++) {
                int row = warp_m * 64 + mt * 16 + a_row;
                uint32_t off = row * 128 + ((k0b + a_c16) ^ ((row & 7) << 4));
                ldsm_x4(a[mt][0], a[mt][1], a[mt][2], a[mt][3], sA + off);
            }
            uint32_t bf[4][2];
#pragma unroll
            for (int pq = 0; pq < 2; pq++) {
                int row = warp_n * 32 + pq * 16 + b_row;
                uint32_t off = row * 128 + ((k0b + b_c16) ^ ((row & 7) << 4));
                ldsm_x4(bf[2 * pq][0], bf[2 * pq][1], bf[2 * pq + 1][0], bf[2 * pq + 1][1],
                        sB + off);
            }
#pragma unroll
            for (int mt = 0; mt < 4; mt++)
#pragma unroll
                for (int nt = 0; nt < 4; nt++)
                    mma_f16(acc[mt][nt][0], acc[mt][nt][1], acc[mt][nt][2], acc[mt][nt][3],
                            a[mt][0], a[mt][1], a[mt][2], a[mt][3],
                            bf[nt][0], bf[nt][1]);
        }
    }

    // ---------------- serial split-K epilogue (self-resetting counters) ----
    if (kz == 0) {
        float bcol[8];
#pragma unroll
        for (int q = 0; q < 4; q++) {
            int col = bn + warp_n * 32 + q * 8 + (lane & 3) * 2;
            bcol[2 * q]     = __ldg(bias + col);
            bcol[2 * q + 1] = __ldg(bias + col + 1);
        }
#pragma unroll
        for (int mt = 0; mt < 4; mt++) {
            int row0 = bm + warp_m * 64 + mt * 16 + (lane >> 2);
#pragma unroll
            for (int nt = 0; nt < 4; nt++) {
                int col = bn + warp_n * 32 + nt * 8 + (lane & 3) * 2;
                float2 v0 = make_float2(acc[mt][nt][0] + bcol[2 * nt],
                                        acc[mt][nt][1] + bcol[2 * nt + 1]);
                float2 v1 = make_float2(acc[mt][nt][2] + bcol[2 * nt],
                                        acc[mt][nt][3] + bcol[2 * nt + 1]);
                *(float2*)(C + (size_t)row0 * OUTF + col)       = v0;
                *(float2*)(C + (size_t)(row0 + 8) * OUTF + col) = v1;
            }
        }
        __threadfence();
        __syncthreads();
        if (tid == 0) atomicAdd(&g_cnt[tile], 1u);
    } else {
        if (tid == 0) {
            while (atomicAdd(&g_cnt[tile], 0u) < (unsigned)kz) __nanosleep(64);
        }
        __syncthreads();
        __threadfence();
#pragma unroll
        for (int mt = 0; mt < 4; mt++) {
            int row0 = bm + warp_m * 64 + mt * 16 + (lane >> 2);
#pragma unroll
            for (int nt = 0; nt < 4; nt++) {
                int col = bn + warp_n * 32 + nt * 8 + (lane & 3) * 2;
                float* p0 = C + (size_t)row0 * OUTF + col;
                float* p1 = C + (size_t)(row0 + 8) * OUTF + col;
                float2 o0 = __ldcg((const float2*)p0);
                float2 o1 = __ldcg((const float2*)p1);
                o0.x += acc[mt][nt][0]; o0.y += acc[mt][nt][1];
                o1.x += acc[mt][nt][2]; o1.y += acc[mt][nt][3];
                *(float2*)p0 = o0;
                *(float2*)p1 = o1;
            }
        }
        __threadfence();
        __syncthreads();
        if (tid == 0) {
            if (kz == SPLITK - 1) atomicExch(&g_cnt[tile], 0u);
            else atomicAdd(&g_cnt[tile], 1u);
        }
    }
}

// ===========================================================================
typedef CUresult (*PFN_encode)(CUtensorMap*, CUtensorMapDataType, cuuint32_t,
                               void*, const cuuint64_t*, const cuuint64_t*,
                               const cuuint32_t*, const cuuint32_t*,
                               CUtensorMapInterleave, CUtensorMapSwizzle,
                               CUtensorMapL2promotion, CUtensorMapFloatOOBfill);

static CUtensorMap s_tma_a, s_tma_w;

static void make_map(PFN_encode enc, CUtensorMap* m, void* base, int rows) {
    cuuint64_t dims[2]    = {(cuuint64_t)K1, (cuuint64_t)rows};
    cuuint64_t strides[1] = {(cuuint64_t)K1 * 2};
    cuuint32_t box[2]     = {KTILE, 128};
    cuuint32_t estr[2]    = {1, 1};
    enc(m, CU_TENSOR_MAP_DATA_TYPE_FLOAT16, 2, base, dims, strides, box, estr,
        CU_TENSOR_MAP_INTERLEAVE_NONE, CU_TENSOR_MAP_SWIZZLE_128B,
        CU_TENSOR_MAP_L2_PROMOTION_L2_128B, CU_TENSOR_MAP_FLOAT_OOB_FILL_NONE);
}

extern "C" void kernel_launch(void* const* d_in, const int* in_sizes, int n_in,
                              void* d_out, int out_size) {
    const float* x    = (const float*)d_in[0];   // [4096,1024]
    const float* bw   = (const float*)d_in[1];   // [1024,1024]
    const float* bias = (const float*)d_in[2];   // [1024]
    const float* sw   = (const float*)d_in[3];   // [1024,1024,8]
    float* out = (float*)d_out;                  // [4096,1024]

    static bool inited = false;
    if (!inited) {
        void* fn = nullptr;
        cudaDriverEntryPointQueryResult st;
        cudaGetDriverEntryPointByVersion("cuTensorMapEncodeTiled", &fn, 12000,
                                         cudaEnableDefault, &st);
        PFN_encode enc = (PFN_encode)fn;
        void *pa = nullptr, *pw = nullptr;
        cudaGetSymbolAddress(&pa, g_A);
        cudaGetSymbolAddress(&pw, g_W);
        make_map(enc, &s_tma_a, pa, NMAT);
        make_map(enc, &s_tma_w, pw, OUTF);
        cudaFuncSetAttribute(gemm_kernel,
                             cudaFuncAttributeMaxDynamicSharedMemorySize, SMEM_TOTAL);
        inited = true;
    }

    prep_kernel<<<BLK_A + BLK_W, 256>>>(x, bw, sw);

    dim3 grid(OUTF / BN, NMAT / BM, SPLITK);   // (8, 32, 4) = 1024 CTAs
    gemm_kernel<<<grid, THREADS, SMEM_TOTAL>>>(s_tma_a, s_tma_w, bias, out);
}

// round 16
// speedup vs baseline: 1.1863x; 1.0580x over previous
#include <cuda_runtime.h>
#include <cuda.h>
#include <cuda_fp16.h>
#include <cstdint>
#include <math.h>

#define NMAT 4096
#define INF  1024
#define OUTF 1024
#define NB   8
#define K1   9216
#define KTILE 64                   // fp16 per k-chunk = 128 bytes (SW128 atom)
#define KCH (K1 / KTILE)           // 144
#define SPLITK 4
#define KT_PER (KCH / SPLITK)      // 36
#define BM 128
#define BN 128
#define STAGES 3
#define THREADS 256                // 8 warps, 2x4 grid of 64x32 warp tiles

#define TILE_BYTES (BM * 128)                  // 16384 per operand
#define STAGE_BYTES (2 * TILE_BYTES)           // 32768
#define SM_STAGE(s) (1024 + (s) * STAGE_BYTES)
#define SMEM_TOTAL (1024 + STAGES * STAGE_BYTES)   // 99328
#define NTILES 256

#define BLK_A (NMAT * INF / 256)       // 16384 blocks for build_A
#define BLK_W (OUTF * INF / 2 / 256)   // 2048 blocks for pack_W (2 elems/thread)

// ---------------- scratch (__device__ globals; no allocs allowed) ----------
__device__ __align__(128) __half g_A[(size_t)NMAT * K1];
__device__ __align__(128) __half g_W[(size_t)OUTF * K1];
__device__ unsigned g_cnt[NTILES];   // zero-init; self-resetting each run

// ---------------- PTX helpers (family-portable only: sm_90 class) ----------
__device__ __forceinline__ uint32_t smem_u32(const void* p) {
    uint32_t a;
    asm("{ .reg .u64 t; cvta.to.shared.u64 t, %1; cvt.u32.u64 %0, t; }" : "=r"(a) : "l"(p));
    return a;
}
#define MBAR_INIT(addr, cnt) \
    asm volatile("mbarrier.init.shared.b64 [%0], %1;" :: "r"(addr), "r"(cnt) : "memory")
#define MBAR_EXPECT_TX(addr, bytes) \
    asm volatile("mbarrier.arrive.expect_tx.shared.b64 _, [%0], %1;" :: "r"(addr), "r"(bytes) : "memory")
#define MBAR_WAIT(addr, ph) do {                                              \
    uint32_t _m = (addr); uint32_t _p = (ph); uint32_t _d;                    \
    asm volatile("{\n .reg .pred p;\n"                                        \
        " mbarrier.try_wait.parity.acquire.cta.shared::cta.b64 p, [%1], %2;\n"\
        " selp.b32 %0, 1, 0, p;\n}" : "=r"(_d) : "r"(_m), "r"(_p) : "memory");\
    if (!_d) {                                                                \
        asm volatile("{\n .reg .pred P1;\n"                                   \
            "W_%=:\n"                                                         \
            " mbarrier.try_wait.parity.acquire.cta.shared::cta.b64 P1, [%0], %1, 0x989680;\n" \
            " @P1 bra.uni D_%=;\n bra.uni W_%=;\nD_%=:\n}"                    \
            :: "r"(_m), "r"(_p) : "memory");                                  \
    }                                                                         \
} while (0)

__device__ __forceinline__ void tma_load_2d(uint32_t dst, const void* map,
                                            int cx, int cy, uint32_t mbar) {
    asm volatile(
        "cp.async.bulk.tensor.2d.shared::cta.global.tile.mbarrier::complete_tx::bytes "
        "[%0], [%1, {%2, %3}], [%4];"
        :: "r"(dst), "l"(map), "r"(cx), "r"(cy), "r"(mbar) : "memory");
}
__device__ __forceinline__ void ldsm_x4(uint32_t& r0, uint32_t& r1, uint32_t& r2,
                                        uint32_t& r3, uint32_t addr) {
    asm volatile("ldmatrix.sync.aligned.m8n8.x4.shared.b16 {%0,%1,%2,%3}, [%4];"
                 : "=r"(r0), "=r"(r1), "=r"(r2), "=r"(r3) : "r"(addr));
}
__device__ __forceinline__ void mma_f16(float& c0, float& c1, float& c2, float& c3,
                                        uint32_t a0, uint32_t a1, uint32_t a2, uint32_t a3,
                                        uint32_t b0, uint32_t b1) {
    asm volatile("mma.sync.aligned.m16n8k16.row.col.f32.f16.f16.f32 "
                 "{%0,%1,%2,%3}, {%4,%5,%6,%7}, {%8,%9}, {%0,%1,%2,%3};"
                 : "+f"(c0), "+f"(c1), "+f"(c2), "+f"(c3)
                 : "r"(a0), "r"(a1), "r"(a2), "r"(a3), "r"(b0), "r"(b1));
}

// ===========================================================================
// Fused prep: blocks [0, BLK_A) build A (Cox-de Boor lattice, proven),
//             blocks [BLK_A, BLK_A+BLK_W) pack W (half2 stores)
// ===========================================================================
__global__ void prep_kernel(const float* __restrict__ x,
                            const float* __restrict__ bw,
                            const float* __restrict__ sw) {
    int blk = blockIdx.x;
    if (blk < BLK_A) {
        int idx = blk * 256 + threadIdx.x;
        float v = x[idx];

        float vals[9];
        vals[0] = v / (1.0f + __expf(-v));   // SiLU

        const float h = 0.4f, lo = -1.0f;
        float b[11];
#pragma unroll
        for (int j = 0; j < 11; j++) {
            float t0 = (float)(j - 3) * h + lo;
            float t1 = (float)(j - 2) * h + lo;
            b[j] = (v >= t0 && v < t1) ? 1.0f : 0.0f;
        }
#pragma unroll
        for (int k = 1; k <= 3; k++) {
            float inv = 1.0f / ((float)k * h + 1e-8f);
#pragma unroll
            for (int j = 0; j + k < 11; j++) {
                float tj   = (float)(j - 3) * h + lo;
                float tjk1 = (float)(j + k - 2) * h + lo;
                b[j] = (v - tj) * inv * b[j] + (tjk1 - v) * inv * b[j + 1];
            }
        }
#pragma unroll
        for (int j = 0; j < NB; j++) vals[1 + j] = b[j];

        size_t rb = (size_t)(idx >> 10) * K1 + (idx & 1023);
#pragma unroll
        for (int s = 0; s < 9; s++)
            g_A[rb + s * 1024] = __float2half_rn(vals[s]);
    } else {
        int idx2 = (blk - BLK_A) * 256 + threadIdx.x;
        int o = idx2 >> 9;
        int i = (idx2 & 511) * 2;
        size_t rb = (size_t)o * K1 + i;

        float2 b2 = ((const float2*)bw)[idx2];
        *(__half2*)(g_W + rb) = __floats2half2_rn(b2.x, b2.y);

        const float4* s4 = (const float4*)(sw + ((size_t)o * INF + i) * NB);
        float4 p0 = s4[0], p1 = s4[1], q0 = s4[2], q1 = s4[3];
        float a0[8] = {p0.x, p0.y, p0.z, p0.w, p1.x, p1.y, p1.z, p1.w};
        float a1[8] = {q0.x, q0.y, q0.z, q0.w, q1.x, q1.y, q1.z, q1.w};
#pragma unroll
        for (int j = 0; j < NB; j++)
            *(__half2*)(g_W + rb + (size_t)(j + 1) * 1024) =
                __floats2half2_rn(a0[j], a1[j]);
    }
}

// ===========================================================================
// GEMM: 128x128 tile, 8 warps (2x4 grid of 64x32 warp tiles), TMA + mbarrier
// pipeline (3 stages, prefetch 2), serial split-K 4.
// Inner loop software-pipelined: B frags + A0 loaded first, then each A[mt+1]
// LDSM issued before mt's MMA burst (hides LDSM latency under tensor work).
// ===========================================================================
__global__ void __launch_bounds__(THREADS, 2)
gemm_kernel(const __grid_constant__ CUtensorMap tma_a,
            const __grid_constant__ CUtensorMap tma_w,
            const float* __restrict__ bias, float* __restrict__ C) {
    extern __shared__ __align__(1024) char smem[];
    uint32_t sb = smem_u32(smem);

    const int tid = threadIdx.x;
    const int wid = tid >> 5;
    const int lane = tid & 31;
    const int warp_m = wid & 1;        // 2 warps along M (64 each)
    const int warp_n = wid >> 1;       // 4 warps along N (32 each)
    const int bm = blockIdx.y * BM;
    const int bn = blockIdx.x * BN;
    const int kz = blockIdx.z;
    const int kb0 = kz * KT_PER;
    const int tile = blockIdx.y * gridDim.x + blockIdx.x;

    if (tid == 0) {
#pragma unroll
        for (int s = 0; s < STAGES; s++) MBAR_INIT(sb + s * 8, 1);
    }
    __syncthreads();

    if (tid == 0) {
#pragma unroll
        for (int j = 0; j < 2; j++) {
            uint32_t st = sb + SM_STAGE(j);
            MBAR_EXPECT_TX(sb + j * 8, STAGE_BYTES);
            tma_load_2d(st,              &tma_a, (kb0 + j) * KTILE, bm, sb + j * 8);
            tma_load_2d(st + TILE_BYTES, &tma_w, (kb0 + j) * KTILE, bn, sb + j * 8);
        }
    }

    float acc[4][4][4];
#pragma unroll
    for (int i = 0; i < 4; i++)
#pragma unroll
        for (int j = 0; j < 4; j++)
#pragma unroll
            for (int q = 0; q < 4; q++) acc[i][j][q] = 0.0f;

    const int a_row = lane & 15;
    const int a_c16 = (lane >> 4) << 4;
    const int b_row = ((lane >> 4) << 3) + (lane & 7);
    const int b_c16 = ((lane >> 3) & 1) << 4;

    // precomputed per-lane swizzled row offsets (row*128 ^ swizzle-of-row)
    uint32_t a_off[4], b_off[2];
#pragma unroll
    for (int mt = 0; mt < 4; mt++) {
        int row = warp_m * 64 + mt * 16 + a_row;
        a_off[mt] = row * 128 + (((uint32_t)a_c16) ^ ((row & 7) << 4));
    }
#pragma unroll
    for (int pq = 0; pq < 2; pq++) {
        int row = warp_n * 32 + pq * 16 + b_row;
        b_off[pq] = row * 128 + (((uint32_t)b_c16) ^ ((row & 7) << 4));
    }

    for (int j = 0; j < KT_PER; j++) {
        int s = j % STAGES;
        MBAR_WAIT(sb + s * 8, (j / STAGES) & 1);
        __syncthreads();
        if (tid == 0 && j + 2 < KT_PER) {
            int jn = j + 2, sn = jn % STAGES;
            uint32_t st = sb + SM_STAGE(sn);
            MBAR_EXPECT_TX(sb + sn * 8, STAGE_BYTES);
            tma_load_2d(st,              &tma_a, (kb0 + jn) * KTILE, bm, sb + sn * 8);
            tma_load_2d(st + TILE_BYTES, &tma_w, (kb0 + jn) * KTILE, bn, sb + sn * 8);
        }

        uint32_t sA = sb + SM_STAGE(s);
        uint32_t sB = sA + TILE_BYTES;
#pragma unroll
        for (int kk = 0; kk < 4; kk++) {
            // swizzle XOR for this kk (k0b ^ rowbits already folded in offsets)
            uint32_t kx = kk * 32;
            uint32_t bf[4][2];
            // B fragments first (both pairs)
            ldsm_x4(bf[0][0], bf[0][1], bf[1][0], bf[1][1], sB + (b_off[0] ^ kx));
            ldsm_x4(bf[2][0], bf[2][1], bf[3][0], bf[3][1], sB + (b_off[1] ^ kx));
            // A0 next
            uint32_t a_cur[4], a_nxt[4];
            ldsm_x4(a_cur[0], a_cur[1], a_cur[2], a_cur[3], sA + (a_off[0] ^ kx));
#pragma unroll
            for (int mt = 0; mt < 4; mt++) {
                if (mt < 3)
                    ldsm_x4(a_nxt[0], a_nxt[1], a_nxt[2], a_nxt[3],
                            sA + (a_off[mt + 1] ^ kx));
#pragma unroll
                for (int nt = 0; nt < 4; nt++)
                    mma_f16(acc[mt][nt][0], acc[mt][nt][1], acc[mt][nt][2], acc[mt][nt][3],
                            a_cur[0], a_cur[1], a_cur[2], a_cur[3],
                            bf[nt][0], bf[nt][1]);
#pragma unroll
                for (int q = 0; q < 4; q++) a_cur[q] = a_nxt[q];
            }
        }
    }

    // ---------------- serial split-K epilogue (self-resetting counters) ----
    if (kz == 0) {
        float bcol[8];
#pragma unroll
        for (int q = 0; q < 4; q++) {
            int col = bn + warp_n * 32 + q * 8 + (lane & 3) * 2;
            bcol[2 * q]     = __ldg(bias + col);
            bcol[2 * q + 1] = __ldg(bias + col + 1);
        }
#pragma unroll
        for (int mt = 0; mt < 4; mt++) {
            int row0 = bm + warp_m * 64 + mt * 16 + (lane >> 2);
#pragma unroll
            for (int nt = 0; nt < 4; nt++) {
                int col = bn + warp_n * 32 + nt * 8 + (lane & 3) * 2;
                float2 v0 = make_float2(acc[mt][nt][0] + bcol[2 * nt],
                                        acc[mt][nt][1] + bcol[2 * nt + 1]);
                float2 v1 = make_float2(acc[mt][nt][2] + bcol[2 * nt],
                                        acc[mt][nt][3] + bcol[2 * nt + 1]);
                *(float2*)(C + (size_t)row0 * OUTF + col)       = v0;
                *(float2*)(C + (size_t)(row0 + 8) * OUTF + col) = v1;
            }
        }
        __threadfence();
        __syncthreads();
        if (tid == 0) atomicAdd(&g_cnt[tile], 1u);
    } else {
        if (tid == 0) {
            while (atomicAdd(&g_cnt[tile], 0u) < (unsigned)kz) __nanosleep(64);
        }
        __syncthreads();
        __threadfence();
#pragma unroll
        for (int mt = 0; mt < 4; mt++) {
            int row0 = bm + warp_m * 64 + mt * 16 + (lane >> 2);
#pragma unroll
            for (int nt = 0; nt < 4; nt++) {
                int col = bn + warp_n * 32 + nt * 8 + (lane & 3) * 2;
                float* p0 = C + (size_t)row0 * OUTF + col;
                float* p1 = C + (size_t)(row0 + 8) * OUTF + col;
                float2 o0 = __ldcg((const float2*)p0);
                float2 o1 = __ldcg((const float2*)p1);
                o0.x += acc[mt][nt][0]; o0.y += acc[mt][nt][1];
                o1.x += acc[mt][nt][2]; o1.y += acc[mt][nt][3];
                *(float2*)p0 = o0;
                *(float2*)p1 = o1;
            }
        }
        __threadfence();
        __syncthreads();
        if (tid == 0) {
            if (kz == SPLITK - 1) atomicExch(&g_cnt[tile], 0u);
            else atomicAdd(&g_cnt[tile], 1u);
        }
    }
}

// ===========================================================================
typedef CUresult (*PFN_encode)(CUtensorMap*, CUtensorMapDataType, cuuint32_t,
                               void*, const cuuint64_t*, const cuuint64_t*,
                               const cuuint32_t*, const cuuint32_t*,
                               CUtensorMapInterleave, CUtensorMapSwizzle,
                               CUtensorMapL2promotion, CUtensorMapFloatOOBfill);

static CUtensorMap s_tma_a, s_tma_w;

static void make_map(PFN_encode enc, CUtensorMap* m, void* base, int rows) {
    cuuint64_t dims[2]    = {(cuuint64_t)K1, (cuuint64_t)rows};
    cuuint64_t strides[1] = {(cuuint64_t)K1 * 2};
    cuuint32_t box[2]     = {KTILE, 128};
    cuuint32_t estr[2]    = {1, 1};
    enc(m, CU_TENSOR_MAP_DATA_TYPE_FLOAT16, 2, base, dims, strides, box, estr,
        CU_TENSOR_MAP_INTERLEAVE_NONE, CU_TENSOR_MAP_SWIZZLE_128B,
        CU_TENSOR_MAP_L2_PROMOTION_L2_128B, CU_TENSOR_MAP_FLOAT_OOB_FILL_NONE);
}

extern "C" void kernel_launch(void* const* d_in, const int* in_sizes, int n_in,
                              void* d_out, int out_size) {
    const float* x    = (const float*)d_in[0];   // [4096,1024]
    const float* bw   = (const float*)d_in[1];   // [1024,1024]
    const float* bias = (const float*)d_in[2];   // [1024]
    const float* sw   = (const float*)d_in[3];   // [1024,1024,8]
    float* out = (float*)d_out;                  // [4096,1024]

    static bool inited = false;
    if (!inited) {
        void* fn = nullptr;
        cudaDriverEntryPointQueryResult st;
        cudaGetDriverEntryPointByVersion("cuTensorMapEncodeTiled", &fn, 12000,
                                         cudaEnableDefault, &st);
        PFN_encode enc = (PFN_encode)fn;
        void *pa = nullptr, *pw = nullptr;
        cudaGetSymbolAddress(&pa, g_A);
        cudaGetSymbolAddress(&pw, g_W);
        make_map(enc, &s_tma_a, pa, NMAT);
        make_map(enc, &s_tma_w, pw, OUTF);
        cudaFuncSetAttribute(gemm_kernel,
                             cudaFuncAttributeMaxDynamicSharedMemorySize, SMEM_TOTAL);
        inited = true;
    }

    prep_kernel<<<BLK_A + BLK_W, 256>>>(x, bw, sw);

    dim3 grid(OUTF / BN, NMAT / BM, SPLITK);   // (8, 32, 4) = 1024 CTAs
    gemm_kernel<<<grid, THREADS, SMEM_TOTAL>>>(s_tma_a, s_tma_w, bias, out);
}